// round 17
// baseline (speedup 1.0000x reference)
#include <cuda_runtime.h>
#include <cuda_fp16.h>
#include <cstdint>

#define B_  16
#define N_  192
#define H_  128
#define F_  128
#define G_  50
#define NG  3        // atom groups per CTA (256 threads each)
#define TM  128      // tile rows (8 warps x 16)
#define LDA1 72      // rbh row stride (halfs)
#define LDB  136     // weight row stride (halfs)
#define ATOMS (B_ * N_)
#define GRID 152
#define GSTRIDE (GRID * NG)   // 456

// group byte offsets
#define RBH_OFF 0                        // 128*72*2 = 18432
#define FST_OFF 18432                    // 128*50*4 = 25600 float staging
#define WT_OFF  44032                    // 128 floats
#define JR_OFF  44544                    // 128 ints
#define JL_OFF  45056                    // 2 x 192 ints
#define RED_OFF 46592                    // 8*128 floats
#define B1_OFF  50688                    // 128 floats
#define B2_OFF  51200                    // 128 floats
#define CNT_OFF 51712                    // cnt[2] + iscr[8]
#define GRP_BYTES 51776

#define W1_OFF 0                         // 64*136*2  = 17408
#define W2_OFF 17408                     // 128*136*2 = 34816
#define GRP0_OFF 52224
#define SMEM_BYTES (GRP0_OFF + NG * GRP_BYTES)   // 207552

__device__ __half g_nfh[ATOMS * F_];     // fp16 neighbor features
__device__ float  g_agg[ATOMS * F_];

__device__ __forceinline__ float softplus_fast(float x) {
    float ax = fabsf(x);
    return fmaxf(x, 0.0f) + __logf(1.0f + __expf(-ax));
}
__device__ __forceinline__ void gbar(int id, int cnt) {
    asm volatile("bar.sync %0, %1;" :: "r"(id), "r"(cnt) : "memory");
}
__device__ __forceinline__ uint32_t packh2(float a, float b) {
    __half2 h = __floats2half2_rn(a, b);
    return *reinterpret_cast<uint32_t*>(&h);
}

#define LDSM4(R, ADDR) \
    asm volatile("ldmatrix.sync.aligned.m8n8.x4.shared.b16 {%0,%1,%2,%3}, [%4];" \
        : "=r"((R)[0]), "=r"((R)[1]), "=r"((R)[2]), "=r"((R)[3]) : "r"(ADDR))
#define LDSM4T(R, ADDR) \
    asm volatile("ldmatrix.sync.aligned.m8n8.x4.trans.shared.b16 {%0,%1,%2,%3}, [%4];" \
        : "=r"((R)[0]), "=r"((R)[1]), "=r"((R)[2]), "=r"((R)[3]) : "r"(ADDR))
#define MMA16816(C, A, B0, B1) \
    asm volatile("mma.sync.aligned.m16n8k16.row.col.f32.f16.f16.f32 " \
        "{%0,%1,%2,%3}, {%4,%5,%6,%7}, {%8,%9}, {%0,%1,%2,%3};" \
        : "+f"((C)[0]), "+f"((C)[1]), "+f"((C)[2]), "+f"((C)[3]) \
        : "r"((A)[0]), "r"((A)[1]), "r"((A)[2]), "r"((A)[3]), "r"(B0), "r"(B1))
#define CP_ASYNC8(DST, SRC) \
    asm volatile("cp.async.ca.shared.global [%0], [%1], 8;" :: "r"(DST), "l"(SRC))
#define CP_COMMIT() asm volatile("cp.async.commit_group;" ::: "memory")
#define CP_WAIT0()  asm volatile("cp.async.wait_group 0;" ::: "memory")

// ---------------------------------------------------------------------------
// nf = features @ W_f + b_f, tiled 16 rows/CTA, fp16 output
#define NF_R 16
__global__ __launch_bounds__(256)
void nf_kernel(const float* __restrict__ features,
               const float* __restrict__ W_f,
               const float* __restrict__ b_f) {
    __shared__ float fs[NF_R][128];
    const int r0   = blockIdx.x * NF_R;
    const int tid  = threadIdx.x;
    const int col  = tid & 127;
    const int half = tid >> 7;

    for (int i = tid; i < NF_R * 128; i += 256)
        fs[i >> 7][i & 127] = features[(size_t)r0 * 128 + i];
    __syncthreads();

    float acc[NF_R / 2];
#pragma unroll
    for (int r = 0; r < NF_R / 2; ++r) acc[r] = b_f[col];
    for (int f = 0; f < 128; ++f) {
        const float w = W_f[f * 128 + col];
#pragma unroll
        for (int r = 0; r < NF_R / 2; ++r)
            acc[r] = fmaf(fs[half + 2 * r][f], w, acc[r]);
    }
#pragma unroll
    for (int r = 0; r < NF_R / 2; ++r)
        g_nfh[(size_t)(r0 + half + 2 * r) * 128 + col] = __float2half_rn(acc[r]);
}

// ---------------------------------------------------------------------------
__device__ __forceinline__ void compact_mask(const int* __restrict__ mb, int* jl,
                                             int* cnt_slot, int* iscr,
                                             int gtid, int wg, int lane, int barid) {
    const int m = (gtid < N_) ? mb[gtid] : 0;
    int v = m;
#pragma unroll
    for (int o = 1; o < 32; o <<= 1) {
        int nv = __shfl_up_sync(0xffffffffu, v, o);
        if (lane >= o) v += nv;
    }
    if (lane == 31) iscr[wg] = v;
    gbar(barid, 256);
    int base = 0;
    for (int w = 0; w < wg; ++w) base += iscr[w];
    if (gtid < N_ && m) jl[base + v - m] = gtid;
    if (gtid == 0) {
        int c = 0;
#pragma unroll
        for (int w = 0; w < 8; ++w) c += iscr[w];
        cnt_slot[0] = c;
    }
    gbar(barid, 256);
}

// 8-byte async gather of compacted rows (rows are 200B, 8B-aligned)
__device__ __forceinline__ void issue_gather(const float* __restrict__ rbfb,
                                             const int* __restrict__ jl, int cnt,
                                             uint32_t fst_sa, int gtid) {
    for (int idx = gtid; idx < TM * 25; idx += 256) {
        const int r  = (idx * 5243) >> 17;    // idx / 25
        const int c2 = (idx - r * 25) * 2;
        if (r < cnt) {
            const float* src = rbfb + (size_t)jl[r] * G_ + c2;
            CP_ASYNC8(fst_sa + idx * 8, src);
        }
    }
    CP_COMMIT();
}

__device__ __forceinline__ void convert_fst(const float* __restrict__ fst,
                                            __half* rbh, float* wt, int* jr,
                                            const int* __restrict__ jl, int cnt, int gtid) {
    for (int idx = gtid; idx < TM * 25; idx += 256) {
        const int r  = (idx * 5243) >> 17;
        const int c2 = (idx - r * 25) * 2;
        float2 v = make_float2(0.0f, 0.0f);
        if (r < cnt) v = *(const float2*)(fst + idx * 2);
        *(__half2*)(rbh + r * LDA1 + c2) = __floats2half2_rn(v.x, v.y);
    }
    if (gtid < TM) {
        const bool ok = gtid < cnt;
        wt[gtid] = ok ? 1.0f : 0.0f;
        jr[gtid] = ok ? jl[gtid] : 0;
    }
}

// ---------------------------------------------------------------------------
__global__ __launch_bounds__(768, 1)
void interaction_kernel(const float* __restrict__ rbf,
                        const int*   __restrict__ nmask,
                        const float* __restrict__ W1,
                        const float* __restrict__ b1,
                        const float* __restrict__ W2,
                        const float* __restrict__ b2) {
    extern __shared__ char smem[];
    const uint32_t sb = (uint32_t)__cvta_generic_to_shared(smem);

    const int tid  = threadIdx.x;
    const int g    = tid >> 8;
    const int gtid = tid & 255;
    const int wg   = gtid >> 5;
    const int lane = tid & 31;

    __half* W1h = (__half*)(smem + W1_OFF);
    __half* W2h = (__half*)(smem + W2_OFF);
    char*   gsm = smem + GRP0_OFF + g * GRP_BYTES;
    __half* rbh   = (__half*)(gsm + RBH_OFF);
    float*  fst   = (float*)(gsm + FST_OFF);
    float*  wt_s  = (float*)(gsm + WT_OFF);
    int*    jr_s  = (int*)(gsm + JR_OFF);
    int*    jl0   = (int*)(gsm + JL_OFF);
    float*  red   = (float*)(gsm + RED_OFF);
    float*  b1_s  = (float*)(gsm + B1_OFF);
    float*  b2_s  = (float*)(gsm + B2_OFF);
    int*    cnt_s = (int*)(gsm + CNT_OFF);          // [2]
    int*    iscr  = cnt_s + 2;                      // [8]

    const uint32_t fst_sa = sb + (uint32_t)(GRP0_OFF + g * GRP_BYTES + FST_OFF);

    // ---- stage weights fp16 once ----
    for (int idx = tid; idx < 64 * F_; idx += 768) {
        const int k = idx >> 7, n = idx & 127;
        W1h[k * LDB + n] = __float2half_rn((k < G_) ? W1[k * F_ + n] : 0.0f);
    }
    for (int idx = tid; idx < F_ * F_; idx += 768) {
        const int k = idx >> 7, n = idx & 127;
        W2h[k * LDB + n] = __float2half_rn(W2[idx]);
    }
    if (gtid < 128) { b1_s[gtid] = b1[gtid]; b2_s[gtid] = b2[gtid]; }
    for (int idx = gtid; idx < 8 * 128; idx += 256) red[idx] = 0.0f;
    for (int idx = gtid; idx < TM * 14; idx += 256) {      // rbh pad cols 50..63
        const int r = idx / 14, c = G_ + idx - (idx / 14) * 14;
        rbh[r * LDA1 + c] = __float2half_rn(0.0f);
    }
    __syncthreads();

    const int first = blockIdx.x * NG + g;
    const int niter = (ATOMS - 1 - first) / GSTRIDE + 1;

    const int qrow = lane >> 2;
    const int qcol = (lane & 3) * 2;
    const int arow = lane & 15;
    const int asel = (lane >> 4) * 8;
    const uint32_t aA1 = sb + (uint32_t)(GRP0_OFF + g * GRP_BYTES + RBH_OFF)
                       + ((wg * 16 + arow) * LDA1 + asel) * 2;
    const uint32_t aW1 = sb + W1_OFF + (arow * LDB + asel) * 2;
    const uint32_t aW2 = sb + W2_OFF + (arow * LDB + asel) * 2;

    // ---- prologue: compact + gather + convert atom 0 ----
    int p = 0;
    {
        compact_mask(nmask + (size_t)first * N_, jl0, cnt_s, iscr, gtid, wg, lane, g + 1);
        issue_gather(rbf + (size_t)first * N_ * G_, jl0, cnt_s[0], fst_sa, gtid);
        CP_WAIT0();
        gbar(g + 1, 256);
        convert_fst(fst, rbh, wt_s, jr_s, jl0, cnt_s[0], gtid);
        gbar(g + 1, 256);
    }

    for (int it = 0; it < niter; ++it) {
        const int atom = first + it * GSTRIDE;
        const int cnt  = cnt_s[p];
        const bool hasnext = (it + 1) < niter;
        const int  b  = atom / N_;
        const __half* nf_b = g_nfh + (size_t)b * N_ * F_;
        int* jlc = jl0 + p * 192;
        int* jln = jl0 + (p ^ 1) * 192;

        // ---- issue next atom's compaction + async gather ----
        if (hasnext) {
            const int nxt = atom + GSTRIDE;
            compact_mask(nmask + (size_t)nxt * N_, jln, cnt_s + (p ^ 1), iscr,
                         gtid, wg, lane, g + 1);
            issue_gather(rbf + (size_t)nxt * N_ * G_, jln, cnt_s[p ^ 1], fst_sa, gtid);
        }

        // ---- compute tiles of current atom ----
        const int tcount = (cnt + TM - 1) >> 7;     // 1 except cnt>128 (rare)
        for (int t = 0; t < tcount; ++t) {
            if (t) {   // rare slow path: sync re-gather rows 128..cnt-1
                gbar(g + 1, 256);
                const float* rbfb = rbf + (size_t)atom * N_ * G_;
                for (int idx = gtid; idx < TM * G_; idx += 256) {
                    const int r = (idx * 5243) >> 18;
                    const int c = idx - r * G_;
                    const int rowpos = t * TM + r;
                    float v = 0.0f;
                    if (rowpos < cnt) v = rbfb[(size_t)jlc[rowpos] * G_ + c];
                    rbh[r * LDA1 + c] = __float2half_rn(v);
                }
                if (gtid < TM) {
                    const int rowpos = t * TM + gtid;
                    const bool ok = rowpos < cnt;
                    wt_s[gtid] = ok ? 1.0f : 0.0f;
                    jr_s[gtid] = ok ? jlc[rowpos] : 0;
                }
                gbar(g + 1, 256);
            }

            if (t * TM + wg * 16 < cnt) {
                // GEMM1: [16,64]@[64,128] in two n-halves -> softplus -> A2 regs
                uint32_t A2[8][4];
#pragma unroll
                for (int h2 = 0; h2 < 2; ++h2) {
                    float c1[8][4];
#pragma unroll
                    for (int nb = 0; nb < 8; ++nb) {
                        const float2 bv = *(const float2*)(b1_s + h2 * 64 + nb * 8 + qcol);
                        c1[nb][0] = bv.x; c1[nb][1] = bv.y;
                        c1[nb][2] = bv.x; c1[nb][3] = bv.y;
                    }
#pragma unroll
                    for (int ks = 0; ks < 4; ++ks) {
                        uint32_t a[4];
                        LDSM4(a, aA1 + ks * 32);
#pragma unroll
                        for (int pp = 0; pp < 4; ++pp) {
                            uint32_t bb[4];
                            LDSM4T(bb, aW1 + (ks * 16 * LDB + h2 * 64 + pp * 16) * 2);
                            MMA16816(c1[pp * 2],     a, bb[0], bb[1]);
                            MMA16816(c1[pp * 2 + 1], a, bb[2], bb[3]);
                        }
                    }
#pragma unroll
                    for (int gk = 0; gk < 4; ++gk) {
                        A2[h2 * 4 + gk][0] = packh2(softplus_fast(c1[2 * gk][0]),
                                                    softplus_fast(c1[2 * gk][1]));
                        A2[h2 * 4 + gk][1] = packh2(softplus_fast(c1[2 * gk][2]),
                                                    softplus_fast(c1[2 * gk][3]));
                        A2[h2 * 4 + gk][2] = packh2(softplus_fast(c1[2 * gk + 1][0]),
                                                    softplus_fast(c1[2 * gk + 1][1]));
                        A2[h2 * 4 + gk][3] = packh2(softplus_fast(c1[2 * gk + 1][2]),
                                                    softplus_fast(c1[2 * gk + 1][3]));
                    }
                }

                // GEMM2: [16,128]@[128,128] in 4 n-chunks + fused aggregation
                const int r0 = wg * 16 + qrow;
                const float w0 = wt_s[r0];
                const float w1 = wt_s[r0 + 8];
                const __half* nr0 = nf_b + (size_t)jr_s[r0] * F_;
                const __half* nr1 = nf_b + (size_t)jr_s[r0 + 8] * F_;
                float* redw = red + wg * 128;
#pragma unroll
                for (int ch = 0; ch < 4; ++ch) {
                    const int cc0 = ch * 32;
                    // prefetch nf half2 for this chunk BEFORE the MMA block
                    __half2 pv0[4], pv1[4];
#pragma unroll
                    for (int ni = 0; ni < 4; ++ni) {
                        const int cc = cc0 + ni * 8 + qcol;
                        pv0[ni] = *(const __half2*)(nr0 + cc);
                        pv1[ni] = *(const __half2*)(nr1 + cc);
                    }
                    float c2[4][4];
#pragma unroll
                    for (int ni = 0; ni < 4; ++ni) {
                        const float2 bv = *(const float2*)(b2_s + cc0 + ni * 8 + qcol);
                        c2[ni][0] = bv.x; c2[ni][1] = bv.y;
                        c2[ni][2] = bv.x; c2[ni][3] = bv.y;
                    }
#pragma unroll
                    for (int ks = 0; ks < 8; ++ks) {
                        uint32_t bb0[4], bb1[4];
                        LDSM4T(bb0, aW2 + (ks * 16 * LDB + cc0) * 2);
                        LDSM4T(bb1, aW2 + (ks * 16 * LDB + cc0 + 16) * 2);
                        MMA16816(c2[0], A2[ks], bb0[0], bb0[1]);
                        MMA16816(c2[1], A2[ks], bb0[2], bb0[3]);
                        MMA16816(c2[2], A2[ks], bb1[0], bb1[1]);
                        MMA16816(c2[3], A2[ks], bb1[2], bb1[3]);
                    }
#pragma unroll
                    for (int ni = 0; ni < 4; ++ni) {
                        const int cc = cc0 + ni * 8 + qcol;
                        const float2 v0 = __half22float2(pv0[ni]);
                        const float2 v1 = __half22float2(pv1[ni]);
                        float s0 = c2[ni][0] * w0 * v0.x + c2[ni][2] * w1 * v1.x;
                        float s1 = c2[ni][1] * w0 * v0.y + c2[ni][3] * w1 * v1.y;
                        s0 += __shfl_xor_sync(0xffffffffu, s0, 4);
                        s0 += __shfl_xor_sync(0xffffffffu, s0, 8);
                        s0 += __shfl_xor_sync(0xffffffffu, s0, 16);
                        s1 += __shfl_xor_sync(0xffffffffu, s1, 4);
                        s1 += __shfl_xor_sync(0xffffffffu, s1, 8);
                        s1 += __shfl_xor_sync(0xffffffffu, s1, 16);
                        if (lane < 4) {
                            redw[cc]     += s0;
                            redw[cc + 1] += s1;
                        }
                    }
                }
            }
        }
        gbar(g + 1, 256);

        // ---- reduce + store agg to global; MLP is a separate kernel ----
        if (gtid < 128) {
            float a = 0.0f;
#pragma unroll
            for (int w = 0; w < 8; ++w) {
                a += red[w * 128 + gtid];
                red[w * 128 + gtid] = 0.0f;
            }
            g_agg[(size_t)atom * F_ + gtid] = a;
        }

        // ---- land next atom's gather, convert to fp16 ----
        CP_WAIT0();
        gbar(g + 1, 256);
        if (hasnext) {
            convert_fst(fst, rbh, wt_s, jr_s, jln, cnt_s[p ^ 1], gtid);
            gbar(g + 1, 256);
        }
        p ^= 1;
    }
}

// ---------------------------------------------------------------------------
// out = softplus(agg @ Wo1 + bo1) @ Wo2 + bo2 + features, tiled 16 rows/CTA
#define OUT_R 16
__global__ __launch_bounds__(256)
void out_kernel(const float* __restrict__ Wo1,
                const float* __restrict__ bo1,
                const float* __restrict__ Wo2,
                const float* __restrict__ bo2,
                const float* __restrict__ features,
                float*       __restrict__ out) {
    __shared__ float aggs[OUT_R][128];
    __shared__ float t1s[OUT_R][128];
    const int r0   = blockIdx.x * OUT_R;
    const int tid  = threadIdx.x;
    const int col  = tid & 127;
    const int half = tid >> 7;

    for (int i = tid; i < OUT_R * 128; i += 256)
        aggs[i >> 7][i & 127] = g_agg[(size_t)r0 * 128 + i];
    __syncthreads();

    float acc[OUT_R / 2];
#pragma unroll
    for (int r = 0; r < OUT_R / 2; ++r) acc[r] = bo1[col];
    for (int f = 0; f < 128; ++f) {
        const float w = Wo1[f * 128 + col];
#pragma unroll
        for (int r = 0; r < OUT_R / 2; ++r)
            acc[r] = fmaf(aggs[half + 2 * r][f], w, acc[r]);
    }
#pragma unroll
    for (int r = 0; r < OUT_R / 2; ++r)
        t1s[half + 2 * r][col] = softplus_fast(acc[r]);
    __syncthreads();

#pragma unroll
    for (int r = 0; r < OUT_R / 2; ++r) acc[r] = bo2[col];
    for (int f = 0; f < 128; ++f) {
        const float w = Wo2[f * 128 + col];
#pragma unroll
        for (int r = 0; r < OUT_R / 2; ++r)
            acc[r] = fmaf(t1s[half + 2 * r][f], w, acc[r]);
    }
#pragma unroll
    for (int r = 0; r < OUT_R / 2; ++r) {
        const size_t row = r0 + half + 2 * r;
        out[row * 128 + col] = acc[r] + features[row * 128 + col];
    }
}

// ---------------------------------------------------------------------------
extern "C" void kernel_launch(void* const* d_in, const int* in_sizes, int n_in,
                              void* d_out, int out_size) {
    const float* features = (const float*)d_in[0];
    const float* rbf      = (const float*)d_in[1];
    const int*   nmask    = (const int*)  d_in[2];
    const float* W_rbf1   = (const float*)d_in[3];
    const float* b_rbf1   = (const float*)d_in[4];
    const float* W_rbf2   = (const float*)d_in[5];
    const float* b_rbf2   = (const float*)d_in[6];
    const float* W_f      = (const float*)d_in[7];
    const float* b_f      = (const float*)d_in[8];
    const float* W_o1     = (const float*)d_in[9];
    const float* b_o1     = (const float*)d_in[10];
    const float* W_o2     = (const float*)d_in[11];
    const float* b_o2     = (const float*)d_in[12];
    float* out = (float*)d_out;

    static int configured = -1;
    if (configured < 0) {
        cudaFuncSetAttribute(interaction_kernel,
                             cudaFuncAttributeMaxDynamicSharedMemorySize, SMEM_BYTES);
        configured = 1;
    }

    nf_kernel<<<ATOMS / NF_R, 256>>>(features, W_f, b_f);
    interaction_kernel<<<GRID, 768, SMEM_BYTES>>>(
        rbf, nmask, W_rbf1, b_rbf1, W_rbf2, b_rbf2);
    out_kernel<<<ATOMS / OUT_R, 256>>>(W_o1, b_o1, W_o2, b_o2, features, out);
}